// round 11
// baseline (speedup 1.0000x reference)
#include <cuda_runtime.h>
#include <cuda_fp16.h>
#include <cstdint>

#define KN 131072
#define KK 16
#define KM 128
#define KD 64
#define BN 128   // n-rows per CTA (4 warps x 32 rows)

#define LOG2E 1.4426950408889634f
#define LN2   0.6931471805599453f

// Per-expert tile (16896 B): [0,16384) fp16 'a' fragments (log2e-scaled),
//   one uint4 per (ks, m-tile-pair, lane) = B regs for TWO m-tiles
// [16384,16896): bias row, 128 floats * log2e
#define TILE_BYTES 16896
#define TILE_U4    (TILE_BYTES / 16)       // 1056
__device__ __align__(16) unsigned char g_bt[KK * TILE_BYTES];   // 264 KB, L2-resident
__device__ float g_ss[KK];                                      // s * ln2

__global__ void prep(const float* __restrict__ a, const float* __restrict__ b,
                     const float* __restrict__ s) {
    int idx = blockIdx.x * 256 + threadIdx.x;
    if (idx < 65536) {
        int c  = idx & 3;
        int l  = (idx >> 2) & 31;
        int mp = (idx >> 7) & 7;
        int ks = (idx >> 10) & 3;
        int k  = idx >> 12;
        int mt = mp * 2 + (c >> 1);
        int r  = c & 1;
        int m  = mt * 8 + (l >> 2);
        int d0 = ks * 16 + (l & 3) * 2 + r * 8;
        const float* am = a + ((size_t)k * KM + m) * KD + d0;
        __half2 h = __floats2half2_rn(am[0] * LOG2E, am[1] * LOG2E);
        *(uint32_t*)(g_bt + (size_t)k * TILE_BYTES +
                     ((((ks * 8 + mp) * 32 + l) * 4 + c) << 2)) = *(const uint32_t*)&h;
    } else if (idx < 65536 + KK * KM) {
        int j = idx - 65536;
        int k = j >> 7, m = j & 127;
        *(float*)(g_bt + (size_t)k * TILE_BYTES + 16384 + (m << 2)) = b[j] * LOG2E;
        if (j < KK) g_ss[j] = s[j] * LN2;
    }
}

__device__ __forceinline__ void mma16816(float (&c)[4], const uint32_t (&A)[4],
                                         uint32_t b0, uint32_t b1) {
    asm volatile(
        "mma.sync.aligned.m16n8k16.row.col.f32.f16.f16.f32 "
        "{%0,%1,%2,%3}, {%4,%5,%6,%7}, {%8,%9}, {%0,%1,%2,%3};"
        : "+f"(c[0]), "+f"(c[1]), "+f"(c[2]), "+f"(c[3])
        : "r"(A[0]), "r"(A[1]), "r"(A[2]), "r"(A[3]), "r"(b0), "r"(b1));
}
__device__ __forceinline__ uint32_t smem_u32(const void* p) {
    uint32_t a;
    asm("{ .reg .u64 t; cvta.to.shared.u64 t, %1; cvt.u32.u64 %0, t; }" : "=r"(a) : "l"(p));
    return a;
}
__device__ __forceinline__ void cp16(uint32_t s, const void* g) {
    asm volatile("cp.async.cg.shared.global [%0], [%1], 16;" :: "r"(s), "l"(g));
}
#define CP_COMMIT() asm volatile("cp.async.commit_group;" ::: "memory")
#define CP_WAIT(n)  asm volatile("cp.async.wait_group %0;" :: "n"(n) : "memory")
__device__ __forceinline__ float ex2f(float v) {
    float r; asm("ex2.approx.f32 %0, %1;" : "=f"(r) : "f"(v)); return r;
}
__device__ __forceinline__ float lg2f(float v) {
    float r; asm("lg2.approx.f32 %0, %1;" : "=f"(r) : "f"(v)); return r;
}
__device__ __forceinline__ uint32_t packh(float a, float b) {
    __half2 h = __floats2half2_rn(a, b);
    return *(const uint32_t*)&h;
}

#define DYN_SMEM (2 * TILE_BYTES)   // 33792 B double buffer

// 128 threads = 4 warps; each warp owns 32 n-rows. All inner-loop shared
// accesses are base[lane] + compile-time-const -> LDS [R+imm], no per-load
// address arithmetic.
__global__ __launch_bounds__(128, 4)
void madk11(const float* __restrict__ x, float* __restrict__ out)
{
    extern __shared__ __align__(16) uint4 smem4[];

    const int tid = threadIdx.x;
    const int w = tid >> 5, l = tid & 31;
    const int g = l >> 2, q = l & 3;
    const int row0 = blockIdx.x * BN + w * 32 + g;

    // ---- prefetch expert 0 ----
    {
        uint32_t dst = smem_u32(smem4);
        const char* src = (const char*)g_bt;
        #pragma unroll
        for (int i = 0; i < 9; ++i) {
            int o = tid + i * 128;
            if (o < TILE_U4) cp16(dst + o * 16, src + o * 16);
        }
        CP_COMMIT();
    }

    // ---- A fragments: two 16-row fragments ----
    uint32_t X[2][4][4];
    #pragma unroll
    for (int p = 0; p < 2; ++p) {
        #pragma unroll
        for (int ks = 0; ks < 4; ++ks) {
            #pragma unroll
            for (int h = 0; h < 2; ++h) {
                int d = ks * 16 + q * 2 + h * 8;
                int r = row0 + p * 16;
                float2 v0 = __ldg((const float2*)(x + (size_t)r * KD + d));
                float2 v1 = __ldg((const float2*)(x + (size_t)(r + 8) * KD + d));
                X[p][ks][h * 2 + 0] = packh(v0.x, v0.y);
                X[p][ks][h * 2 + 1] = packh(v1.x, v1.y);
            }
        }
    }

    float res0 = 0.f, res1 = 0.f, res2 = 0.f, res3 = 0.f;

    #pragma unroll 1
    for (int k = 0; k < KK; ++k) {
        CP_WAIT(0);
        __syncthreads();

        if (k + 1 < KK) {
            uint32_t dst = smem_u32(smem4 + ((k + 1) & 1) * TILE_U4);
            const char* src = (const char*)(g_bt + (size_t)(k + 1) * TILE_BYTES);
            #pragma unroll
            for (int i = 0; i < 9; ++i) {
                int o = tid + i * 128;
                if (o < TILE_U4) cp16(dst + o * 16, src + o * 16);
            }
            CP_COMMIT();
        }

        // per-expert bases; all inner offsets are compile-time constants
        const uint4*  abv = smem4 + (k & 1) * TILE_U4 + l;            // B frags
        const float2* bv  = (const float2*)(smem4 + (k & 1) * TILE_U4 + 1024) + q;  // bias
        float s0 = 0.f, s1 = 0.f, s2 = 0.f, s3 = 0.f;

        #pragma unroll
        for (int ch = 0; ch < 4; ++ch) {
            // bias (log2e-scaled) as initial accumulator
            float acc0[4][4], acc1[4][4];
            #pragma unroll
            for (int mt = 0; mt < 4; ++mt) {
                float2 bb = bv[(ch * 4 + mt) * 4];
                acc0[mt][0] = bb.x; acc0[mt][1] = bb.y;
                acc0[mt][2] = bb.x; acc0[mt][3] = bb.y;
                acc1[mt][0] = bb.x; acc1[mt][1] = bb.y;
                acc1[mt][2] = bb.x; acc1[mt][3] = bb.y;
            }

            // 8 LDS.128 [R+imm]: each uint4 feeds 4 MMAs
            uint4 B[4][2];
            #pragma unroll
            for (int ks = 0; ks < 4; ++ks)
                #pragma unroll
                for (int mp = 0; mp < 2; ++mp)
                    B[ks][mp] = abv[(ks * 8 + ch * 2 + mp) * 32];

            #pragma unroll
            for (int ks = 0; ks < 4; ++ks) {
                #pragma unroll
                for (int mp = 0; mp < 2; ++mp) {
                    mma16816(acc0[mp * 2 + 0], X[0][ks], B[ks][mp].x, B[ks][mp].y);
                    mma16816(acc1[mp * 2 + 0], X[1][ks], B[ks][mp].x, B[ks][mp].y);
                    mma16816(acc0[mp * 2 + 1], X[0][ks], B[ks][mp].z, B[ks][mp].w);
                    mma16816(acc1[mp * 2 + 1], X[1][ks], B[ks][mp].z, B[ks][mp].w);
                }
            }

            // fused epilogue: acc = (x@a + b)*log2e
            #pragma unroll
            for (int mt = 0; mt < 4; ++mt) {
                s0 += ex2f(acc0[mt][0]);
                s0 += ex2f(acc0[mt][1]);
                s1 += ex2f(acc0[mt][2]);
                s1 += ex2f(acc0[mt][3]);
                s2 += ex2f(acc1[mt][0]);
                s2 += ex2f(acc1[mt][1]);
                s3 += ex2f(acc1[mt][2]);
                s3 += ex2f(acc1[mt][3]);
            }
        }

        s0 += __shfl_xor_sync(0xffffffffu, s0, 1);
        s0 += __shfl_xor_sync(0xffffffffu, s0, 2);
        s1 += __shfl_xor_sync(0xffffffffu, s1, 1);
        s1 += __shfl_xor_sync(0xffffffffu, s1, 2);
        s2 += __shfl_xor_sync(0xffffffffu, s2, 1);
        s2 += __shfl_xor_sync(0xffffffffu, s2, 2);
        s3 += __shfl_xor_sync(0xffffffffu, s3, 1);
        s3 += __shfl_xor_sync(0xffffffffu, s3, 2);

        float sv = g_ss[k];                 // s * ln2
        res0 = fmaf(sv, lg2f(s0), res0);
        res1 = fmaf(sv, lg2f(s1), res1);
        res2 = fmaf(sv, lg2f(s2), res2);
        res3 = fmaf(sv, lg2f(s3), res3);
    }

    if (q == 0) {
        out[row0]      = res0;
        out[row0 + 8]  = res1;
        out[row0 + 16] = res2;
        out[row0 + 24] = res3;
    }
}

extern "C" void kernel_launch(void* const* d_in, const int* in_sizes, int n_in,
                              void* d_out, int out_size)
{
    const float* x = (const float*)d_in[0];   // [131072, 64]
    const float* s = (const float*)d_in[1];   // [16]
    const float* a = (const float*)d_in[2];   // [16, 128, 64]
    const float* b = (const float*)d_in[3];   // [16, 128]
    float* out = (float*)d_out;

    cudaFuncSetAttribute(madk11, cudaFuncAttributeMaxDynamicSharedMemorySize, DYN_SMEM);

    prep<<<(65536 + KK * KM + 255) / 256, 256>>>(a, b, s);
    madk11<<<KN / BN, 128, DYN_SMEM>>>(x, out);
}